// round 3
// baseline (speedup 1.0000x reference)
#include <cuda_runtime.h>
#include <cuda_bf16.h>
#include <cstdint>

#define FULL 0xFFFFFFFFu

__device__ __forceinline__ float2 cmul(float2 a, float2 b) {
    return make_float2(fmaf(a.x, b.x, -a.y * b.y),
                       fmaf(a.x, b.y,  a.y * b.x));
}

// ---------------------------------------------------------------------------
// Layout: one warp per token. Lane l holds amplitudes flat=(k<<5)|l, k=0..7.
// Wire w <-> flat bit (7-w). flat bits 0..4 = lane bits (wires 7..3),
// flat bits 5..7 = k bits k0,k1,k2 (wires 2,1,0).
// ---------------------------------------------------------------------------

template<int RB>
__device__ __forceinline__ void rx_reg(float2 (&a)[8], float c, float s) {
#pragma unroll
    for (int k0 = 0; k0 < 8; ++k0) {
        if (k0 & (1 << RB)) continue;
        const int k1 = k0 | (1 << RB);
        float2 A = a[k0], B = a[k1];
        a[k0].x = fmaf(c, A.x,  s * B.y);
        a[k0].y = fmaf(c, A.y, -s * B.x);
        a[k1].x = fmaf(c, B.x,  s * A.y);
        a[k1].y = fmaf(c, B.y, -s * A.x);
    }
}

template<int B>
__device__ __forceinline__ void rx_lane(float2 (&a)[8], float c, float s) {
#pragma unroll
    for (int k = 0; k < 8; ++k) {
        float px = __shfl_xor_sync(FULL, a[k].x, 1 << B);
        float py = __shfl_xor_sync(FULL, a[k].y, 1 << B);
        float nx = fmaf(c, a[k].x,  s * py);
        float ny = fmaf(c, a[k].y, -s * px);
        a[k].x = nx; a[k].y = ny;
    }
}

template<int W>
__device__ __forceinline__ void rx_wire(float2 (&a)[8], float c, float s) {
    constexpr int B = 7 - W;
    if constexpr (B >= 5) rx_reg<B - 5>(a, c, s);
    else                  rx_lane<B>(a, c, s);
}

template<int W>
__device__ __forceinline__ void rz_wire(float2 (&a)[8], int lane, float c, float s) {
    constexpr int B = 7 - W;
#pragma unroll
    for (int k = 0; k < 8; ++k) {
        int bit;
        if constexpr (B >= 5) bit = (k >> (B - 5)) & 1;
        else                  bit = (lane >> B) & 1;
        float t = bit ? s : -s;
        float nx = fmaf(a[k].x, c, -a[k].y * t);
        float ny = fmaf(a[k].y, c,  a[k].x * t);
        a[k].x = nx; a[k].y = ny;
    }
}

template<int BC, int BT>
__device__ __forceinline__ void cnot(float2 (&a)[8], int lane) {
    if constexpr (BC >= 5 && BT >= 5) {
#pragma unroll
        for (int k = 0; k < 8; ++k) {
            if ((k & (1 << (BC - 5))) && !(k & (1 << (BT - 5)))) {
                const int k2 = k | (1 << (BT - 5));
                float2 t = a[k]; a[k] = a[k2]; a[k2] = t;
            }
        }
    } else if constexpr (BC >= 5 && BT < 5) {
#pragma unroll
        for (int k = 0; k < 8; ++k) {
            if (k & (1 << (BC - 5))) {
                a[k].x = __shfl_xor_sync(FULL, a[k].x, 1 << BT);
                a[k].y = __shfl_xor_sync(FULL, a[k].y, 1 << BT);
            }
        }
    } else if constexpr (BC < 5 && BT >= 5) {
        const bool cset = (lane >> BC) & 1;
#pragma unroll
        for (int k0 = 0; k0 < 8; ++k0) {
            if (!(k0 & (1 << (BT - 5)))) {
                const int k1 = k0 | (1 << (BT - 5));
                float2 A = a[k0], B = a[k1];
                a[k0] = cset ? B : A;
                a[k1] = cset ? A : B;
            }
        }
    } else {
        const bool cset = (lane >> BC) & 1;
#pragma unroll
        for (int k = 0; k < 8; ++k) {
            float px = __shfl_xor_sync(FULL, a[k].x, 1 << BT);
            float py = __shfl_xor_sync(FULL, a[k].y, 1 << BT);
            if (cset) { a[k].x = px; a[k].y = py; }
        }
    }
}

// ---------------------------------------------------------------------------
// Fused kernel: block b = bs row b. 8 warps = 8 heads. Each warp runs the
// quantum layer for its token, deposits 8 expectation values in smem, then the
// block applies W_combine for its row.
// ---------------------------------------------------------------------------
__global__ void __launch_bounds__(256)
fused_kernel(const float* __restrict__ x,
             const float* __restrict__ params_rx,
             const float* __restrict__ params_rz,
             const float* __restrict__ Wc,
             float* __restrict__ out,
             int depth)
{
    __shared__ float cRx[64], sRx[64], cRz[64], sRz[64];
    __shared__ float qs[64];

    const int tid = threadIdx.x;
    const int dp8 = depth * 8;
    if (tid < dp8) {
        float s_, c_;
        sincosf(params_rx[tid] * 0.5f, &s_, &c_);
        sRx[tid] = s_; cRx[tid] = c_;
    } else if (tid < 2 * dp8) {
        const int i = tid - dp8;
        float s_, c_;
        sincosf(params_rz[i] * 0.5f, &s_, &c_);
        sRz[i] = s_; cRz[i] = c_;
    }
    __syncthreads();

    const int lane = tid & 31;
    const int h    = tid >> 5;       // head = warp id
    const int bs   = blockIdx.x;

    // ---- Fused encoding + layer-0 RX: phi_w = x_w + prx[0,w] ----
    float myc = 0.f, mys = 0.f;
    if (lane < 8) {
        const float ang = x[bs * 64 + h * 8 + lane] + params_rx[lane];
        sincosf(ang * 0.5f, &mys, &myc);
    }

    float uc[8], us[8];
#pragma unroll
    for (int w = 0; w < 8; ++w) {
        uc[w] = __shfl_sync(FULL, myc, w);
        us[w] = __shfl_sync(FULL, mys, w);
    }

    // Per-wire single-qubit vectors after layer-0 RZ:
    // u0 = e^{-i th/2} cos, u1 = -i e^{i th/2} sin
    float2 u0[8], u1[8];
#pragma unroll
    for (int w = 0; w < 8; ++w) {
        const float cz = cRz[w], sz = sRz[w];
        u0[w] = make_float2( cz * uc[w], -sz * uc[w]);
        u1[w] = make_float2( sz * us[w], -cz * us[w]);
    }

    // ---- Direct construction of Ring0( product state ) ----
    const int f0 = lane & 1, f1 = (lane >> 1) & 1, f2 = (lane >> 2) & 1;
    const int f3 = (lane >> 3) & 1, f4 = (lane >> 4) & 1;

    const int b4 = f3 ^ f4, b5 = f2 ^ f3, b6 = f1 ^ f2, b7 = f0 ^ f1;
    float2 L = cmul(cmul(b4 ? u1[4] : u0[4], b5 ? u1[5] : u0[5]),
                    cmul(b6 ? u1[6] : u0[6], b7 ? u1[7] : u0[7]));

    float2 A[4], B[4];
#pragma unroll
    for (int j = 0; j < 4; ++j) {
        const int jk2 = j >> 1, jk1 = j & 1;
        A[j] = cmul((jk2 ^ f0) ? u1[0] : u0[0],
                    (jk1 ^ jk2 ^ f0) ? u1[1] : u0[1]);
    }
#pragma unroll
    for (int j = 0; j < 4; ++j) {
        const int jk1 = j >> 1, jk0 = j & 1;
        B[j] = cmul((jk0 ^ jk1) ? u1[2] : u0[2],
                    (f4 ^ jk0) ? u1[3] : u0[3]);
    }

    float2 a[8];
#pragma unroll
    for (int k = 0; k < 8; ++k)
        a[k] = cmul(L, cmul(A[(k >> 1) & 3], B[k & 3]));

    // ---- Middle layers (full), l = 1 .. depth-2 ----
    for (int l = 1; l < depth - 1; ++l) {
        const int base = l * 8;
#define APPLY_LW(W) do {                                             \
            rx_wire<(W)>(a, cRx[base + (W)], sRx[base + (W)]);       \
            rz_wire<(W)>(a, lane, cRz[base + (W)], sRz[base + (W)]); \
        } while (0)
        APPLY_LW(0); APPLY_LW(1); APPLY_LW(2); APPLY_LW(3);
        APPLY_LW(4); APPLY_LW(5); APPLY_LW(6); APPLY_LW(7);
#undef APPLY_LW
        cnot<7, 6>(a, lane);
        cnot<6, 5>(a, lane);
        cnot<5, 4>(a, lane);
        cnot<4, 3>(a, lane);
        cnot<3, 2>(a, lane);
        cnot<2, 1>(a, lane);
        cnot<1, 0>(a, lane);
        cnot<0, 7>(a, lane);
    }

    float z0, z1, z2, z3, z4, z5, z6, z7;

    if (depth >= 2) {
        // ---- Last layer: RX only (RZ dropped, ring folded into observables) ----
        const int base = (depth - 1) * 8;
        rx_wire<0>(a, cRx[base + 0], sRx[base + 0]);
        rx_wire<1>(a, cRx[base + 1], sRx[base + 1]);
        rx_wire<2>(a, cRx[base + 2], sRx[base + 2]);
        rx_wire<3>(a, cRx[base + 3], sRx[base + 3]);
        rx_wire<4>(a, cRx[base + 4], sRx[base + 4]);
        rx_wire<5>(a, cRx[base + 5], sRx[base + 5]);
        rx_wire<6>(a, cRx[base + 6], sRx[base + 6]);
        rx_wire<7>(a, cRx[base + 7], sRx[base + 7]);

        float p[8];
#pragma unroll
        for (int k = 0; k < 8; ++k)
            p[k] = fmaf(a[k].x, a[k].x, a[k].y * a[k].y);

        float sK = 0.f, s01 = 0.f, s12 = 0.f;
#pragma unroll
        for (int k = 0; k < 8; ++k) {
            const int pk  = __popc(k) & 1;
            const int p01 = __popc(k & 3) & 1;
            const int p12 = __popc(k >> 1) & 1;
            sK  += pk  ? -p[k] : p[k];
            s01 += p01 ? -p[k] : p[k];
            s12 += p12 ? -p[k] : p[k];
        }

        const int m3 = f4;
        const int m4 = m3 ^ f3;
        const int m5 = m4 ^ f2;
        const int m6 = m5 ^ f1;
        const int m7 = m6 ^ f0;

        z0 = m7 ? -s01 : s01;
        z1 = s12;
        z2 = sK;
        z3 = m3 ? -sK : sK;
        z4 = m4 ? -sK : sK;
        z5 = m5 ? -sK : sK;
        z6 = m6 ? -sK : sK;
        z7 = m7 ? -sK : sK;
    } else {
        float p[8];
#pragma unroll
        for (int k = 0; k < 8; ++k)
            p[k] = fmaf(a[k].x, a[k].x, a[k].y * a[k].y);
        float sA = 0.f, s0 = 0.f, s1 = 0.f, s2 = 0.f;
#pragma unroll
        for (int k = 0; k < 8; ++k) {
            sA += p[k];
            s0 += ((k >> 2) & 1) ? -p[k] : p[k];
            s1 += ((k >> 1) & 1) ? -p[k] : p[k];
            s2 += ((k     ) & 1) ? -p[k] : p[k];
        }
        z0 = s0; z1 = s1; z2 = s2;
        z3 = f4 ? -sA : sA;
        z4 = f3 ? -sA : sA;
        z5 = f2 ? -sA : sA;
        z6 = f1 ? -sA : sA;
        z7 = f0 ? -sA : sA;
    }

#pragma unroll
    for (int off = 16; off; off >>= 1) {
        z0 += __shfl_xor_sync(FULL, z0, off);
        z1 += __shfl_xor_sync(FULL, z1, off);
        z2 += __shfl_xor_sync(FULL, z2, off);
        z3 += __shfl_xor_sync(FULL, z3, off);
        z4 += __shfl_xor_sync(FULL, z4, off);
        z5 += __shfl_xor_sync(FULL, z5, off);
        z6 += __shfl_xor_sync(FULL, z6, off);
        z7 += __shfl_xor_sync(FULL, z7, off);
    }

    if (lane == 0) {
        float* q = qs + h * 8;
        q[0] = z0; q[1] = z1; q[2] = z2; q[3] = z3;
        q[4] = z4; q[5] = z5; q[6] = z6; q[7] = z7;
    }
    __syncthreads();

    // ---- Combine: warp h computes out[bs, h*8 .. h*8+8) ----
    // lane = p*8 + eo ; output e = h*8+eo ; partial over j = p*16 .. p*16+16
    const int eo = lane & 7;
    const int p_ = lane >> 3;
    const int e  = h * 8 + eo;

    const float4* q4 = reinterpret_cast<const float4*>(qs + p_ * 16);
    const float4* w4 = reinterpret_cast<const float4*>(Wc + e * 64 + p_ * 16);

    float acc = 0.f;
#pragma unroll
    for (int i = 0; i < 4; ++i) {
        const float4 qv = q4[i];
        const float4 wv = w4[i];
        acc = fmaf(qv.x, wv.x, acc);
        acc = fmaf(qv.y, wv.y, acc);
        acc = fmaf(qv.z, wv.z, acc);
        acc = fmaf(qv.w, wv.w, acc);
    }
    acc += __shfl_xor_sync(FULL, acc, 8);
    acc += __shfl_xor_sync(FULL, acc, 16);

    if (p_ == 0)
        out[bs * 64 + e] = acc;
}

// ---------------------------------------------------------------------------
extern "C" void kernel_launch(void* const* d_in, const int* in_sizes, int n_in,
                              void* d_out, int out_size)
{
    const float* x    = (const float*)d_in[0];      // [B,S,64]
    const float* prx  = (const float*)d_in[1];      // [depth,8]
    const float* prz  = (const float*)d_in[2];      // [depth,8]
    const float* W    = (const float*)d_in[3];      // [64,64]
    float* out        = (float*)d_out;              // [B,S,64]

    const int BS    = in_sizes[0] / 64;             // 2048
    const int depth = in_sizes[1] / 8;              // 2

    fused_kernel<<<BS, 256>>>(x, prx, prz, W, out, depth);
}

// round 4
// speedup vs baseline: 1.1092x; 1.1092x over previous
#include <cuda_runtime.h>
#include <cuda_bf16.h>
#include <cstdint>

#define FULL 0xFFFFFFFFu

__device__ __forceinline__ float2 cmul(float2 a, float2 b) {
    return make_float2(fmaf(a.x, b.x, -a.y * b.y),
                       fmaf(a.x, b.y,  a.y * b.x));
}

// ---------------------------------------------------------------------------
// Layout: one warp per token. Lane l holds amplitudes flat=(k<<5)|l, k=0..7.
// Wire w <-> flat bit (7-w). flat bits 0..4 = lane bits (wires 7..3),
// flat bits 5..7 = k bits k0,k1,k2 (wires 2,1,0).
// ---------------------------------------------------------------------------

template<int RB>
__device__ __forceinline__ void rx_reg(float2 (&a)[8], float c, float s) {
#pragma unroll
    for (int k0 = 0; k0 < 8; ++k0) {
        if (k0 & (1 << RB)) continue;
        const int k1 = k0 | (1 << RB);
        float2 A = a[k0], B = a[k1];
        a[k0].x = fmaf(c, A.x,  s * B.y);
        a[k0].y = fmaf(c, A.y, -s * B.x);
        a[k1].x = fmaf(c, B.x,  s * A.y);
        a[k1].y = fmaf(c, B.y, -s * A.x);
    }
}

template<int B>
__device__ __forceinline__ void rx_lane(float2 (&a)[8], float c, float s) {
#pragma unroll
    for (int k = 0; k < 8; ++k) {
        float px = __shfl_xor_sync(FULL, a[k].x, 1 << B);
        float py = __shfl_xor_sync(FULL, a[k].y, 1 << B);
        float nx = fmaf(c, a[k].x,  s * py);
        float ny = fmaf(c, a[k].y, -s * px);
        a[k].x = nx; a[k].y = ny;
    }
}

template<int W>
__device__ __forceinline__ void rx_wire(float2 (&a)[8], float c, float s) {
    constexpr int B = 7 - W;
    if constexpr (B >= 5) rx_reg<B - 5>(a, c, s);
    else                  rx_lane<B>(a, c, s);
}

template<int W>
__device__ __forceinline__ void rz_wire(float2 (&a)[8], int lane, float c, float s) {
    constexpr int B = 7 - W;
#pragma unroll
    for (int k = 0; k < 8; ++k) {
        int bit;
        if constexpr (B >= 5) bit = (k >> (B - 5)) & 1;
        else                  bit = (lane >> B) & 1;
        float t = bit ? s : -s;
        float nx = fmaf(a[k].x, c, -a[k].y * t);
        float ny = fmaf(a[k].y, c,  a[k].x * t);
        a[k].x = nx; a[k].y = ny;
    }
}

template<int BC, int BT>
__device__ __forceinline__ void cnot(float2 (&a)[8], int lane) {
    if constexpr (BC >= 5 && BT >= 5) {
#pragma unroll
        for (int k = 0; k < 8; ++k) {
            if ((k & (1 << (BC - 5))) && !(k & (1 << (BT - 5)))) {
                const int k2 = k | (1 << (BT - 5));
                float2 t = a[k]; a[k] = a[k2]; a[k2] = t;
            }
        }
    } else if constexpr (BC >= 5 && BT < 5) {
#pragma unroll
        for (int k = 0; k < 8; ++k) {
            if (k & (1 << (BC - 5))) {
                a[k].x = __shfl_xor_sync(FULL, a[k].x, 1 << BT);
                a[k].y = __shfl_xor_sync(FULL, a[k].y, 1 << BT);
            }
        }
    } else if constexpr (BC < 5 && BT >= 5) {
        const bool cset = (lane >> BC) & 1;
#pragma unroll
        for (int k0 = 0; k0 < 8; ++k0) {
            if (!(k0 & (1 << (BT - 5)))) {
                const int k1 = k0 | (1 << (BT - 5));
                float2 A = a[k0], B = a[k1];
                a[k0] = cset ? B : A;
                a[k1] = cset ? A : B;
            }
        }
    } else {
        const bool cset = (lane >> BC) & 1;
#pragma unroll
        for (int k = 0; k < 8; ++k) {
            float px = __shfl_xor_sync(FULL, a[k].x, 1 << BT);
            float py = __shfl_xor_sync(FULL, a[k].y, 1 << BT);
            if (cset) { a[k].x = px; a[k].y = py; }
        }
    }
}

// ---------------------------------------------------------------------------
// Fused kernel: block b = bs row b. 8 warps = 8 heads.
// ---------------------------------------------------------------------------
template<bool D2>
__global__ void __launch_bounds__(256)
fused_kernel(const float* __restrict__ x,
             const float* __restrict__ params_rx,
             const float* __restrict__ params_rz,
             const float* __restrict__ Wc,
             float* __restrict__ out,
             int depth)
{
    __shared__ float cRx[64], sRx[64], cRz[64], sRz[64];
    __shared__ float qs[64];

    const int tid = threadIdx.x;
    const int dp8 = depth * 8;
    if (tid < dp8) {
        float s_, c_;
        sincosf(params_rx[tid] * 0.5f, &s_, &c_);
        sRx[tid] = s_; cRx[tid] = c_;
    } else if (tid < 2 * dp8) {
        const int i = tid - dp8;
        float s_, c_;
        sincosf(params_rz[i] * 0.5f, &s_, &c_);
        sRz[i] = s_; cRz[i] = c_;
    }
    __syncthreads();

    const int lane = tid & 31;
    const int h    = tid >> 5;
    const int bs   = blockIdx.x;

    // ---- Fused encoding + layer-0 RX: phi_w = x_w + prx[0,w] ----
    float myc = 0.f, mys = 0.f;
    if (lane < 8) {
        const float ang = x[bs * 64 + h * 8 + lane] + params_rx[lane];
        __sincosf(ang * 0.5f, &mys, &myc);
    }

    float uc[8], us[8];
#pragma unroll
    for (int w = 0; w < 8; ++w) {
        uc[w] = __shfl_sync(FULL, myc, w);
        us[w] = __shfl_sync(FULL, mys, w);
    }

    // Per-wire single-qubit vectors after layer-0 RZ.
    float2 u0[8], u1[8];
#pragma unroll
    for (int w = 0; w < 8; ++w) {
        const float cz = cRz[w], sz = sRz[w];
        u0[w] = make_float2( cz * uc[w], -sz * uc[w]);
        u1[w] = make_float2( sz * us[w], -cz * us[w]);
    }

    // ---- Direct construction of Ring0( product state ) ----
    const int f0 = lane & 1, f1 = (lane >> 1) & 1, f2 = (lane >> 2) & 1;
    const int f3 = (lane >> 3) & 1, f4 = (lane >> 4) & 1;

    const int b4 = f3 ^ f4, b5 = f2 ^ f3, b6 = f1 ^ f2, b7 = f0 ^ f1;
    float2 L = cmul(cmul(b4 ? u1[4] : u0[4], b5 ? u1[5] : u0[5]),
                    cmul(b6 ? u1[6] : u0[6], b7 ? u1[7] : u0[7]));

    float2 A[4], LB[4];
#pragma unroll
    for (int j = 0; j < 4; ++j) {
        const int jk2 = j >> 1, jk1 = j & 1;
        A[j] = cmul((jk2 ^ f0) ? u1[0] : u0[0],
                    (jk1 ^ jk2 ^ f0) ? u1[1] : u0[1]);
    }
#pragma unroll
    for (int j = 0; j < 4; ++j) {
        const int jk1 = j >> 1, jk0 = j & 1;
        float2 B = cmul((jk0 ^ jk1) ? u1[2] : u0[2],
                        (f4 ^ jk0) ? u1[3] : u0[3]);
        LB[j] = cmul(L, B);
    }

    float2 a[8];
#pragma unroll
    for (int k = 0; k < 8; ++k)
        a[k] = cmul(A[(k >> 1) & 3], LB[k & 3]);

    // ---- Middle layers (only when depth > 2) ----
    if constexpr (!D2) {
        for (int l = 1; l < depth - 1; ++l) {
            const int base = l * 8;
#define APPLY_LW(W) do {                                             \
                rx_wire<(W)>(a, cRx[base + (W)], sRx[base + (W)]);   \
                rz_wire<(W)>(a, lane, cRz[base + (W)], sRz[base + (W)]); \
            } while (0)
            APPLY_LW(0); APPLY_LW(1); APPLY_LW(2); APPLY_LW(3);
            APPLY_LW(4); APPLY_LW(5); APPLY_LW(6); APPLY_LW(7);
#undef APPLY_LW
            cnot<7, 6>(a, lane);
            cnot<6, 5>(a, lane);
            cnot<5, 4>(a, lane);
            cnot<4, 3>(a, lane);
            cnot<3, 2>(a, lane);
            cnot<2, 1>(a, lane);
            cnot<1, 0>(a, lane);
            cnot<0, 7>(a, lane);
        }
    }

    float z0, z1, z2, z3, z4, z5, z6, z7;

    if (D2 || depth >= 2) {
        // ---- Last layer: RX only (RZ dropped, ring folded into observables) ----
        const int base = (depth - 1) * 8;
        rx_wire<0>(a, cRx[base + 0], sRx[base + 0]);
        rx_wire<1>(a, cRx[base + 1], sRx[base + 1]);
        rx_wire<2>(a, cRx[base + 2], sRx[base + 2]);
        rx_wire<3>(a, cRx[base + 3], sRx[base + 3]);
        rx_wire<4>(a, cRx[base + 4], sRx[base + 4]);
        rx_wire<5>(a, cRx[base + 5], sRx[base + 5]);
        rx_wire<6>(a, cRx[base + 6], sRx[base + 6]);
        rx_wire<7>(a, cRx[base + 7], sRx[base + 7]);

        float p[8];
#pragma unroll
        for (int k = 0; k < 8; ++k)
            p[k] = fmaf(a[k].x, a[k].x, a[k].y * a[k].y);

        // Folded observables: Z0 -> Z1..Z7 ; Zw -> Z0..Zw (w>=1)
        float sK = 0.f, s01 = 0.f, s12 = 0.f;
#pragma unroll
        for (int k = 0; k < 8; ++k) {
            const int pk  = __popc(k) & 1;
            const int p01 = __popc(k & 3) & 1;
            const int p12 = __popc(k >> 1) & 1;
            sK  += pk  ? -p[k] : p[k];
            s01 += p01 ? -p[k] : p[k];
            s12 += p12 ? -p[k] : p[k];
        }

        const int m3 = f4;
        const int m4 = m3 ^ f3;
        const int m5 = m4 ^ f2;
        const int m6 = m5 ^ f1;
        const int m7 = m6 ^ f0;

        z0 = m7 ? -s01 : s01;
        z1 = s12;
        z2 = sK;
        z3 = m3 ? -sK : sK;
        z4 = m4 ? -sK : sK;
        z5 = m5 ? -sK : sK;
        z6 = m6 ? -sK : sK;
        z7 = m7 ? -sK : sK;
    } else {
        float p[8];
#pragma unroll
        for (int k = 0; k < 8; ++k)
            p[k] = fmaf(a[k].x, a[k].x, a[k].y * a[k].y);
        float sA = 0.f, s0 = 0.f, s1 = 0.f, s2 = 0.f;
#pragma unroll
        for (int k = 0; k < 8; ++k) {
            sA += p[k];
            s0 += ((k >> 2) & 1) ? -p[k] : p[k];
            s1 += ((k >> 1) & 1) ? -p[k] : p[k];
            s2 += ((k     ) & 1) ? -p[k] : p[k];
        }
        z0 = s0; z1 = s1; z2 = s2;
        z3 = f4 ? -sA : sA;
        z4 = f3 ? -sA : sA;
        z5 = f2 ? -sA : sA;
        z6 = f1 ? -sA : sA;
        z7 = f0 ? -sA : sA;
    }

    // ---- Reduce-scatter: 8 values over 32 lanes in 9 shuffles ----
    // After: every lane holds the total of value v = f0*4 + f1*2 + f2.
    float K0, K1, K2, K3;
    {
        const bool b = lane & 1;                  // f0: keeps z4..7 if set
        float s0 = b ? z0 : z4;
        float s1 = b ? z1 : z5;
        float s2 = b ? z2 : z6;
        float s3 = b ? z3 : z7;
        K0 = (b ? z4 : z0) + __shfl_xor_sync(FULL, s0, 1);
        K1 = (b ? z5 : z1) + __shfl_xor_sync(FULL, s1, 1);
        K2 = (b ? z6 : z2) + __shfl_xor_sync(FULL, s2, 1);
        K3 = (b ? z7 : z3) + __shfl_xor_sync(FULL, s3, 1);
    }
    float J0, J1;
    {
        const bool b = lane & 2;                  // f1: keeps K2,K3 if set
        float s0 = b ? K0 : K2;
        float s1 = b ? K1 : K3;
        J0 = (b ? K2 : K0) + __shfl_xor_sync(FULL, s0, 2);
        J1 = (b ? K3 : K1) + __shfl_xor_sync(FULL, s1, 2);
    }
    float T;
    {
        const bool b = lane & 4;                  // f2: keeps J1 if set
        float s0 = b ? J0 : J1;
        T = (b ? J1 : J0) + __shfl_xor_sync(FULL, s0, 4);
    }
    T += __shfl_xor_sync(FULL, T, 8);
    T += __shfl_xor_sync(FULL, T, 16);

    if (lane < 8) {
        const int v = ((lane & 1) << 2) | (lane & 2) | ((lane >> 2) & 1);
        qs[h * 8 + v] = T;
    }
    __syncthreads();

    // ---- Combine: warp h computes out[bs, h*8 .. h*8+8) ----
    const int eo = lane & 7;
    const int p_ = lane >> 3;
    const int e  = h * 8 + eo;

    const float4* q4 = reinterpret_cast<const float4*>(qs + p_ * 16);
    const float4* w4 = reinterpret_cast<const float4*>(Wc + e * 64 + p_ * 16);

    float acc = 0.f;
#pragma unroll
    for (int i = 0; i < 4; ++i) {
        const float4 qv = q4[i];
        const float4 wv = w4[i];
        acc = fmaf(qv.x, wv.x, acc);
        acc = fmaf(qv.y, wv.y, acc);
        acc = fmaf(qv.z, wv.z, acc);
        acc = fmaf(qv.w, wv.w, acc);
    }
    acc += __shfl_xor_sync(FULL, acc, 8);
    acc += __shfl_xor_sync(FULL, acc, 16);

    if (p_ == 0)
        out[bs * 64 + e] = acc;
}

// ---------------------------------------------------------------------------
extern "C" void kernel_launch(void* const* d_in, const int* in_sizes, int n_in,
                              void* d_out, int out_size)
{
    const float* x    = (const float*)d_in[0];      // [B,S,64]
    const float* prx  = (const float*)d_in[1];      // [depth,8]
    const float* prz  = (const float*)d_in[2];      // [depth,8]
    const float* W    = (const float*)d_in[3];      // [64,64]
    float* out        = (float*)d_out;              // [B,S,64]

    const int BS    = in_sizes[0] / 64;             // 2048
    const int depth = in_sizes[1] / 8;              // 2

    if (depth == 2)
        fused_kernel<true><<<BS, 256>>>(x, prx, prz, W, out, depth);
    else
        fused_kernel<false><<<BS, 256>>>(x, prx, prz, W, out, depth);
}